// round 8
// baseline (speedup 1.0000x reference)
#include <cuda_runtime.h>
#include <math.h>

// Scratch: t[b,s] (B=128, S=4096) + per-batch completion counters
__device__ float g_t[128 * 4096];
__device__ int   g_cnt[1024];        // zero-init; self-resetting each run

#define CH 128                       // rows per chunk (16 octets)

// ---------------------------------------------------------------------------
// Persistent fused kernel. 296 blocks grid-stride over 128-row chunks with
// R5's measured-best quad-mapping stream. The block that completes a batch's
// last chunk runs that batch's stats+head+output epilogue inline.
// ---------------------------------------------------------------------------
__global__ __launch_bounds__(256, 2)
void k_fused(const float* __restrict__ x,
             const float* __restrict__ w1,
             const float* __restrict__ b1,
             const float* __restrict__ w2,
             const float* __restrict__ b2,
             const float* __restrict__ w3,
             const float* __restrict__ b3,
             float* __restrict__ out,
             int rows, int S, int dout)
{
    const int tid  = threadIdx.x;
    const int lane = tid & 31;
    const int q    = lane & 3;              // column slice within quad
    const int sub  = lane >> 2;             // row within octet (0..7)
    const int wid  = tid >> 5;              // 8 warps

    const float4* __restrict__ X = reinterpret_cast<const float4*>(x);
    const float4* __restrict__ W = reinterpret_cast<const float4*>(w1);

    // lane-local weight slices (w1 is (2,128)) — R5 layout
    float4 wa0[8], wa1[8];
    #pragma unroll
    for (int k = 0; k < 8; ++k) { wa0[k] = W[q + 4*k]; wa1[k] = W[32 + q + 4*k]; }
    const float bb0 = b1[0], bb1 = b1[1];
    const float c0 = w2[0], c1 = w2[1], cb = b2[0];

    const int nchunks = rows / CH;          // 4096
    const int cpb     = S / CH;             // chunks per batch = 32

    __shared__ int sh_last;
    __shared__ double sh_s[8], sh_ss[8];
    __shared__ alignas(16) float sh_stats[2];
    __shared__ alignas(16) float sh_o[64];

    for (int ch = blockIdx.x; ch < nchunks; ch += gridDim.x) {
        const int b    = ch / cpb;
        const int row0 = ch * CH;

        // ---- stream this chunk (R5 inner loop, 2 octets per warp) ----
        #pragma unroll
        for (int o = wid; o < (CH >> 3); o += 8) {
            const int row = row0 + (o << 3) + sub;
            const size_t base = (size_t)row * 32 + q;

            float4 v[8];
            #pragma unroll
            for (int k = 0; k < 8; ++k) v[k] = X[base + 4*k];

            float d0 = 0.f, d1 = 0.f;
            #pragma unroll
            for (int k = 0; k < 8; ++k) {
                d0 += v[k].x*wa0[k].x + v[k].y*wa0[k].y + v[k].z*wa0[k].z + v[k].w*wa0[k].w;
                d1 += v[k].x*wa1[k].x + v[k].y*wa1[k].y + v[k].z*wa1[k].z + v[k].w*wa1[k].w;
            }
            d0 += __shfl_xor_sync(0xffffffffu, d0, 1);
            d0 += __shfl_xor_sync(0xffffffffu, d0, 2);
            d1 += __shfl_xor_sync(0xffffffffu, d1, 1);
            d1 += __shfl_xor_sync(0xffffffffu, d1, 2);

            if (q == 0) {
                float h0 = fmaxf(d0 + bb0, 0.0f);
                float h1 = fmaxf(d1 + bb1, 0.0f);
                g_t[row] = fmaf(c1, h1, fmaf(c0, h0, cb));
            }
        }

        // ---- publish chunk; last chunk of the batch runs the epilogue ----
        __threadfence();
        __syncthreads();
        if (tid == 0)
            sh_last = (atomicAdd(&g_cnt[b], 1) == cpb - 1) ? 1 : 0;
        __syncthreads();

        if (sh_last) {
            __threadfence();                 // acquire other blocks' g_t stores

            const int N = S - 2;
            const float* __restrict__ tb = g_t + (size_t)b * S;
            const float4* __restrict__ T4 = reinterpret_cast<const float4*>(tb);

            float fs = 0.f, fss = 0.f;
            const int nq4 = S >> 2;          // 1024 float4 groups
            for (int k = tid; k < nq4; k += 256) {
                float4 A = T4[k];
                float bx = 0.f, by = 0.f;
                if (4*k + 5 < S) {
                    float2 Bv = *reinterpret_cast<const float2*>(tb + 4*k + 4);
                    bx = Bv.x; by = Bv.y;
                }
                float diff[4] = { A.z - A.x, A.w - A.y, bx - A.z, by - A.w };
                const int cnt = min(4, N - 4*k);
                #pragma unroll
                for (int j = 0; j < 4; ++j) {
                    if (j < cnt) {
                        float l = logf(fabsf(diff[j]) + 1e-6f);
                        fs += l;
                        fss = fmaf(l, l, fss);
                    }
                }
            }

            double s = (double)fs, ss = (double)fss;
            #pragma unroll
            for (int off = 16; off; off >>= 1) {
                s  += __shfl_xor_sync(0xffffffffu, s,  off);
                ss += __shfl_xor_sync(0xffffffffu, ss, off);
            }
            if (lane == 0) { sh_s[wid] = s; sh_ss[wid] = ss; }
            __syncthreads();
            if (wid == 0) {
                double ts  = (lane < 8) ? sh_s[lane]  : 0.0;
                double tss = (lane < 8) ? sh_ss[lane] : 0.0;
                #pragma unroll
                for (int off = 4; off; off >>= 1) {
                    ts  += __shfl_xor_sync(0xffffffffu, ts,  off);
                    tss += __shfl_xor_sync(0xffffffffu, tss, off);
                }
                if (lane == 0) {
                    const double Nd = (double)N;
                    double mean = ts / Nd;
                    double var  = (tss - ts * ts / Nd) / (Nd - 1.0);
                    if (var < 0.0) var = 0.0;
                    sh_stats[0] = (float)mean;
                    sh_stats[1] = (float)sqrt(var);
                }
            }
            __syncthreads();

            if (tid < dout)
                sh_o[tid] = tanhf(sh_stats[0] * w3[2*tid] + sh_stats[1] * w3[2*tid + 1] + b3[tid]);
            __syncthreads();

            float4* __restrict__ ob = reinterpret_cast<float4*>(out + (size_t)b * dout * dout);
            const float4* __restrict__ so = reinterpret_cast<const float4*>(sh_o);
            const int total4 = (dout * dout) >> 2;   // 1024
            const int row4   = dout >> 2;            // 16
            for (int k = tid; k < total4; k += 256)
                ob[k] = so[k & (row4 - 1)];

            if (tid == 0) g_cnt[b] = 0;      // reset for next graph replay
            __syncthreads();                 // protect sh_* before next chunk
        }
    }
}

extern "C" void kernel_launch(void* const* d_in, const int* in_sizes, int n_in,
                              void* d_out, int out_size)
{
    const float* x  = (const float*)d_in[0];
    const float* w1 = (const float*)d_in[1];
    const float* b1 = (const float*)d_in[2];
    const float* w2 = (const float*)d_in[3];
    const float* b2 = (const float*)d_in[4];
    const float* w3 = (const float*)d_in[5];
    const float* b3 = (const float*)d_in[6];
    float* out = (float*)d_out;

    const int DOUT = 64;
    const int B    = out_size / (DOUT * DOUT);   // 128
    const int rows = in_sizes[0] / 128;          // B * S
    const int S    = rows / B;                   // 4096

    k_fused<<<296, 256>>>(x, w1, b1, w2, b2, w3, b3, out, rows, S, DOUT);
}

// round 9
// speedup vs baseline: 2.6393x; 2.6393x over previous
#include <cuda_runtime.h>
#include <math.h>

// ---------------------------------------------------------------------------
// Single self-contained kernel: one 512-thread block per batch.
//  Phase 1: stream x[b] (2MB) with the measured-best quad-mapping loop,
//           t[s] -> shared (16.4KB). No global scratch, no fences, no atomics.
//  Phase 2: log-diff stats from shared, tanh head, 16KB output slice.
// ---------------------------------------------------------------------------
__global__ __launch_bounds__(512, 1)
void k_all(const float* __restrict__ x,
           const float* __restrict__ w1,
           const float* __restrict__ b1,
           const float* __restrict__ w2,
           const float* __restrict__ b2,
           const float* __restrict__ w3,
           const float* __restrict__ b3,
           float* __restrict__ out,
           int S, int dout)
{
    extern __shared__ float t_sh[];          // S floats (16KB)
    __shared__ double sh_s[16], sh_ss[16];
    __shared__ alignas(16) float sh_stats[2];
    __shared__ alignas(16) float sh_o[64];

    const int b    = blockIdx.x;
    const int tid  = threadIdx.x;
    const int lane = tid & 31;
    const int q    = lane & 3;               // column slice within quad
    const int sub  = lane >> 2;              // row within octet (0..7)
    const int wid  = tid >> 5;               // 16 warps

    const float4* __restrict__ X = reinterpret_cast<const float4*>(x);
    const float4* __restrict__ W = reinterpret_cast<const float4*>(w1);

    // ---- Phase 1: stream (quad mapping, identical arithmetic to R5) ----
    {
        float4 wa0[8], wa1[8];
        #pragma unroll
        for (int k = 0; k < 8; ++k) { wa0[k] = W[q + 4*k]; wa1[k] = W[32 + q + 4*k]; }
        const float bb0 = b1[0], bb1 = b1[1];
        const float c0 = w2[0], c1 = w2[1], cb = b2[0];

        const int octets = S >> 3;           // 512
        for (int o = wid; o < octets; o += 16) {
            const int row = (o << 3) + sub;  // local row in batch
            const size_t base = ((size_t)b * S + row) * 32 + q;

            float4 v[8];
            #pragma unroll
            for (int k = 0; k < 8; ++k) v[k] = X[base + 4*k];

            float d0 = 0.f, d1 = 0.f;
            #pragma unroll
            for (int k = 0; k < 8; ++k) {
                d0 += v[k].x*wa0[k].x + v[k].y*wa0[k].y + v[k].z*wa0[k].z + v[k].w*wa0[k].w;
                d1 += v[k].x*wa1[k].x + v[k].y*wa1[k].y + v[k].z*wa1[k].z + v[k].w*wa1[k].w;
            }
            d0 += __shfl_xor_sync(0xffffffffu, d0, 1);
            d0 += __shfl_xor_sync(0xffffffffu, d0, 2);
            d1 += __shfl_xor_sync(0xffffffffu, d1, 1);
            d1 += __shfl_xor_sync(0xffffffffu, d1, 2);

            if (q == 0) {
                float h0 = fmaxf(d0 + bb0, 0.0f);
                float h1 = fmaxf(d1 + bb1, 0.0f);
                t_sh[row] = fmaf(c1, h1, fmaf(c0, h0, cb));
            }
        }
    }
    __syncthreads();

    // ---- Phase 2: stats over log|t[i+2]-t[i]|, i in [0, S-2) ----
    const int N = S - 2;
    float fs = 0.f, fss = 0.f;
    for (int i = tid; i < N; i += 512) {
        float d = fabsf(t_sh[i + 2] - t_sh[i]);
        float l = logf(d + 1e-6f);
        fs += l;
        fss = fmaf(l, l, fss);
    }
    double s = (double)fs, ss = (double)fss;
    #pragma unroll
    for (int off = 16; off; off >>= 1) {
        s  += __shfl_xor_sync(0xffffffffu, s,  off);
        ss += __shfl_xor_sync(0xffffffffu, ss, off);
    }
    if (lane == 0) { sh_s[wid] = s; sh_ss[wid] = ss; }
    __syncthreads();
    if (wid == 0) {
        double ts  = (lane < 16) ? sh_s[lane]  : 0.0;
        double tss = (lane < 16) ? sh_ss[lane] : 0.0;
        #pragma unroll
        for (int off = 8; off; off >>= 1) {
            ts  += __shfl_xor_sync(0xffffffffu, ts,  off);
            tss += __shfl_xor_sync(0xffffffffu, tss, off);
        }
        if (lane == 0) {
            const double Nd = (double)N;
            double mean = ts / Nd;
            double var  = (tss - ts * ts / Nd) / (Nd - 1.0);
            if (var < 0.0) var = 0.0;
            sh_stats[0] = (float)mean;
            sh_stats[1] = (float)sqrt(var);
        }
    }
    __syncthreads();

    // ---- head + broadcast output ----
    if (tid < dout)
        sh_o[tid] = tanhf(sh_stats[0] * w3[2*tid] + sh_stats[1] * w3[2*tid + 1] + b3[tid]);
    __syncthreads();

    float4* __restrict__ ob = reinterpret_cast<float4*>(out + (size_t)b * dout * dout);
    const float4* __restrict__ so = reinterpret_cast<const float4*>(sh_o);
    const int total4 = (dout * dout) >> 2;   // 1024
    const int row4   = dout >> 2;            // 16
    for (int k = tid; k < total4; k += 512)
        ob[k] = so[k & (row4 - 1)];
}

extern "C" void kernel_launch(void* const* d_in, const int* in_sizes, int n_in,
                              void* d_out, int out_size)
{
    const float* x  = (const float*)d_in[0];
    const float* w1 = (const float*)d_in[1];
    const float* b1 = (const float*)d_in[2];
    const float* w2 = (const float*)d_in[3];
    const float* b2 = (const float*)d_in[4];
    const float* w3 = (const float*)d_in[5];
    const float* b3 = (const float*)d_in[6];
    float* out = (float*)d_out;

    const int DOUT = 64;
    const int B    = out_size / (DOUT * DOUT);   // 128
    const int rows = in_sizes[0] / 128;          // B * S
    const int S    = rows / B;                   // 4096

    k_all<<<B, 512, S * sizeof(float)>>>(x, w1, b1, w2, b2, w3, b3, out, S, DOUT);
}